// round 1
// baseline (speedup 1.0000x reference)
#include <cuda_runtime.h>

// GraphAttentionPooling: B=32, N=3072, F=256, P=3 -> S=1024
//   x = batch.reshape(B, S, 3, F)
//   scores[b,s,p] = dot(x[b,s,p,:], W) + bias
//   att = softmax(scores over p)
//   out[b,s,f] = sum_p x[b,s,p,f] * att[p]
//
// One warp per window. Lane l owns features [8l, 8l+8) as 2x float4.
// 3 rows kept in registers; 3 warp-shuffle reductions; softmax over 3;
// weighted combine; coalesced float4 stores.

#define F_DIM 256
#define P_DIM 3

__device__ __forceinline__ float warp_reduce_sum(float v) {
    #pragma unroll
    for (int off = 16; off > 0; off >>= 1)
        v += __shfl_xor_sync(0xFFFFFFFFu, v, off);
    return v;
}

__device__ __forceinline__ float dot8(float4 a, float4 b, float4 wa, float4 wb) {
    float s = a.x * wa.x;
    s = fmaf(a.y, wa.y, s);
    s = fmaf(a.z, wa.z, s);
    s = fmaf(a.w, wa.w, s);
    s = fmaf(b.x, wb.x, s);
    s = fmaf(b.y, wb.y, s);
    s = fmaf(b.z, wb.z, s);
    s = fmaf(b.w, wb.w, s);
    return s;
}

__global__ void __launch_bounds__(256, 8)
gap_kernel(const float* __restrict__ x,
           const float* __restrict__ Ww,
           const float* __restrict__ Wb,
           float* __restrict__ out,
           int n_windows) {
    const int warp_id = (blockIdx.x * blockDim.x + threadIdx.x) >> 5;
    const int lane    = threadIdx.x & 31;
    if (warp_id >= n_windows) return;

    // Window base: 3 consecutive rows of F floats.
    const float4* xin = reinterpret_cast<const float4*>(
        x + (size_t)warp_id * (P_DIM * F_DIM));
    // Each lane owns 8 floats = 2 float4 per row. Row stride = 256 floats = 64 float4.
    const int fv = lane * 2;  // float4 index within a row

    // Issue all 6 row loads + 2 weight loads up front (max MLP).
    float4 r0a = xin[0 * 64 + fv], r0b = xin[0 * 64 + fv + 1];
    float4 r1a = xin[1 * 64 + fv], r1b = xin[1 * 64 + fv + 1];
    float4 r2a = xin[2 * 64 + fv], r2b = xin[2 * 64 + fv + 1];
    const float4* Wv = reinterpret_cast<const float4*>(Ww);
    float4 wa = Wv[fv], wb = Wv[fv + 1];

    // Per-lane partial dot products, then warp reduce.
    float s0 = warp_reduce_sum(dot8(r0a, r0b, wa, wb));
    float s1 = warp_reduce_sum(dot8(r1a, r1b, wa, wb));
    float s2 = warp_reduce_sum(dot8(r2a, r2b, wa, wb));

    const float bias = Wb[0];
    s0 += bias; s1 += bias; s2 += bias;

    // Softmax over 3 scores (every lane computes identically; no broadcast needed).
    float m = fmaxf(s0, fmaxf(s1, s2));
    float e0 = __expf(s0 - m);
    float e1 = __expf(s1 - m);
    float e2 = __expf(s2 - m);
    float inv = 1.0f / (e0 + e1 + e2);
    float a0 = e0 * inv, a1 = e1 * inv, a2 = e2 * inv;

    // Weighted combine and store (coalesced float4).
    float4 oa, ob;
    oa.x = fmaf(r2a.x, a2, fmaf(r1a.x, a1, r0a.x * a0));
    oa.y = fmaf(r2a.y, a2, fmaf(r1a.y, a1, r0a.y * a0));
    oa.z = fmaf(r2a.z, a2, fmaf(r1a.z, a1, r0a.z * a0));
    oa.w = fmaf(r2a.w, a2, fmaf(r1a.w, a1, r0a.w * a0));
    ob.x = fmaf(r2b.x, a2, fmaf(r1b.x, a1, r0b.x * a0));
    ob.y = fmaf(r2b.y, a2, fmaf(r1b.y, a1, r0b.y * a0));
    ob.z = fmaf(r2b.z, a2, fmaf(r1b.z, a1, r0b.z * a0));
    ob.w = fmaf(r2b.w, a2, fmaf(r1b.w, a1, r0b.w * a0));

    float4* ov = reinterpret_cast<float4*>(out + (size_t)warp_id * F_DIM);
    ov[fv]     = oa;
    ov[fv + 1] = ob;
}

extern "C" void kernel_launch(void* const* d_in, const int* in_sizes, int n_in,
                              void* d_out, int out_size) {
    const float* x  = (const float*)d_in[0];  // [32, 3072, 256]
    const float* Ww = (const float*)d_in[1];  // [256]
    const float* Wb = (const float*)d_in[2];  // [1]
    float* out = (float*)d_out;               // [32, 1024, 256, 1]

    const int n_windows = in_sizes[0] / (P_DIM * F_DIM);  // 32768
    const int warps_per_block = 8;                        // 256 threads
    const int blocks = (n_windows + warps_per_block - 1) / warps_per_block;

    gap_kernel<<<blocks, warps_per_block * 32>>>(x, Ww, Wb, out, n_windows);
}

// round 2
// speedup vs baseline: 1.0743x; 1.0743x over previous
#include <cuda_runtime.h>

// GraphAttentionPooling: B=32, N=3072, F=256, P=3 -> S=1024, 32768 windows.
// One warp per WPW consecutive windows, software-pipelined (prefetch depth 1).
// Lane l owns features [8l, 8l+8) as 2x float4. Streaming loads/stores (.cs).

#define F_DIM 256
#define P_DIM 3
#define WPW 8

__device__ __forceinline__ float warp_reduce_sum(float v) {
    #pragma unroll
    for (int off = 16; off > 0; off >>= 1)
        v += __shfl_xor_sync(0xFFFFFFFFu, v, off);
    return v;
}

__device__ __forceinline__ float dot8(float4 a, float4 b, float4 wa, float4 wb) {
    float s = a.x * wa.x;
    s = fmaf(a.y, wa.y, s);
    s = fmaf(a.z, wa.z, s);
    s = fmaf(a.w, wa.w, s);
    s = fmaf(b.x, wb.x, s);
    s = fmaf(b.y, wb.y, s);
    s = fmaf(b.z, wb.z, s);
    s = fmaf(b.w, wb.w, s);
    return s;
}

__global__ void __launch_bounds__(256, 2)
gap_kernel(const float* __restrict__ x,
           const float* __restrict__ Ww,
           const float* __restrict__ Wb,
           float* __restrict__ out,
           int n_windows) {
    const int warp_id = (blockIdx.x * blockDim.x + threadIdx.x) >> 5;
    const int lane    = threadIdx.x & 31;
    const long long win0 = (long long)warp_id * WPW;
    if (win0 >= n_windows) return;

    const int fv = lane * 2;  // float4 index within a row (row = 64 float4)

    const float4* Wv = reinterpret_cast<const float4*>(Ww);
    const float4 wa = Wv[fv], wb = Wv[fv + 1];
    const float bias = Wb[0];

    // Window stride: 3 rows * 64 float4 = 192 float4.
    const float4* xin = reinterpret_cast<const float4*>(x) + win0 * 192;
    float4*       ov  = reinterpret_cast<float4*>(out)     + win0 * 64;

    // Prefetch window 0 (streaming, evict-first).
    float4 n0a = __ldcs(xin + 0 * 64 + fv), n0b = __ldcs(xin + 0 * 64 + fv + 1);
    float4 n1a = __ldcs(xin + 1 * 64 + fv), n1b = __ldcs(xin + 1 * 64 + fv + 1);
    float4 n2a = __ldcs(xin + 2 * 64 + fv), n2b = __ldcs(xin + 2 * 64 + fv + 1);

    #pragma unroll
    for (int i = 0; i < WPW; i++) {
        // Current window = last prefetch.
        float4 r0a = n0a, r0b = n0b;
        float4 r1a = n1a, r1b = n1b;
        float4 r2a = n2a, r2b = n2b;

        // Prefetch next window BEFORE the dependent compute chain.
        if (i + 1 < WPW) {
            const float4* nx = xin + (long long)(i + 1) * 192;
            n0a = __ldcs(nx + 0 * 64 + fv); n0b = __ldcs(nx + 0 * 64 + fv + 1);
            n1a = __ldcs(nx + 1 * 64 + fv); n1b = __ldcs(nx + 1 * 64 + fv + 1);
            n2a = __ldcs(nx + 2 * 64 + fv); n2b = __ldcs(nx + 2 * 64 + fv + 1);
        }

        // Scores: per-lane partials + butterfly reduce (all lanes get the sum).
        float s0 = warp_reduce_sum(dot8(r0a, r0b, wa, wb)) + bias;
        float s1 = warp_reduce_sum(dot8(r1a, r1b, wa, wb)) + bias;
        float s2 = warp_reduce_sum(dot8(r2a, r2b, wa, wb)) + bias;

        // Softmax over 3 scores.
        float m = fmaxf(s0, fmaxf(s1, s2));
        float e0 = __expf(s0 - m);
        float e1 = __expf(s1 - m);
        float e2 = __expf(s2 - m);
        float inv = 1.0f / (e0 + e1 + e2);
        float a0 = e0 * inv, a1 = e1 * inv, a2 = e2 * inv;

        // Weighted combine.
        float4 oa, ob;
        oa.x = fmaf(r2a.x, a2, fmaf(r1a.x, a1, r0a.x * a0));
        oa.y = fmaf(r2a.y, a2, fmaf(r1a.y, a1, r0a.y * a0));
        oa.z = fmaf(r2a.z, a2, fmaf(r1a.z, a1, r0a.z * a0));
        oa.w = fmaf(r2a.w, a2, fmaf(r1a.w, a1, r0a.w * a0));
        ob.x = fmaf(r2b.x, a2, fmaf(r1b.x, a1, r0b.x * a0));
        ob.y = fmaf(r2b.y, a2, fmaf(r1b.y, a1, r0b.y * a0));
        ob.z = fmaf(r2b.z, a2, fmaf(r1b.z, a1, r0b.z * a0));
        ob.w = fmaf(r2b.w, a2, fmaf(r1b.w, a1, r0b.w * a0));

        float4* o = ov + (long long)i * 64;
        __stcs(o + fv,     oa);
        __stcs(o + fv + 1, ob);
    }
}

extern "C" void kernel_launch(void* const* d_in, const int* in_sizes, int n_in,
                              void* d_out, int out_size) {
    const float* x  = (const float*)d_in[0];  // [32, 3072, 256]
    const float* Ww = (const float*)d_in[1];  // [256]
    const float* Wb = (const float*)d_in[2];  // [1]
    float* out = (float*)d_out;               // [32, 1024, 256, 1]

    const int n_windows = in_sizes[0] / (P_DIM * F_DIM);      // 32768
    const int n_warps   = (n_windows + WPW - 1) / WPW;        // 4096
    const int warps_per_block = 8;                            // 256 threads
    const int blocks = (n_warps + warps_per_block - 1) / warps_per_block;  // 512

    gap_kernel<<<blocks, warps_per_block * 32>>>(x, Ww, Wb, out, n_windows);
}

// round 3
// speedup vs baseline: 1.3319x; 1.2398x over previous
#include <cuda_runtime.h>

// GraphAttentionPooling: B=32, N=3072, F=256, P=3 -> S=1024, 32768 windows.
// Persistent exact-fit grid (148 SMs x 3 blocks x 8 warps = 3552 warps),
// grid-stride over windows with depth-1 software prefetch.
// Lane l owns features [8l, 8l+8) as 2x float4. Streaming loads/stores (.cs).

#define F_DIM 256
#define P_DIM 3
#define NUM_SMS 148
#define BLOCKS_PER_SM 3
#define THREADS_PER_BLOCK 256

__device__ __forceinline__ float warp_reduce_sum(float v) {
    #pragma unroll
    for (int off = 16; off > 0; off >>= 1)
        v += __shfl_xor_sync(0xFFFFFFFFu, v, off);
    return v;
}

__device__ __forceinline__ float dot8(float4 a, float4 b, float4 wa, float4 wb) {
    float s = a.x * wa.x;
    s = fmaf(a.y, wa.y, s);
    s = fmaf(a.z, wa.z, s);
    s = fmaf(a.w, wa.w, s);
    s = fmaf(b.x, wb.x, s);
    s = fmaf(b.y, wb.y, s);
    s = fmaf(b.z, wb.z, s);
    s = fmaf(b.w, wb.w, s);
    return s;
}

__global__ void __launch_bounds__(THREADS_PER_BLOCK, BLOCKS_PER_SM)
gap_kernel(const float* __restrict__ x,
           const float* __restrict__ Ww,
           const float* __restrict__ Wb,
           float* __restrict__ out,
           int n_windows) {
    const int warp_id   = (blockIdx.x * blockDim.x + threadIdx.x) >> 5;
    const int lane      = threadIdx.x & 31;
    const int n_warps   = (int)((gridDim.x * blockDim.x) >> 5);

    const int fv = lane * 2;  // float4 index within a row (row = 64 float4)

    const float4* Wv = reinterpret_cast<const float4*>(Ww);
    const float4 wa = Wv[fv], wb = Wv[fv + 1];
    const float bias = Wb[0];

    const float4* xbase = reinterpret_cast<const float4*>(x);
    float4*       obase = reinterpret_cast<float4*>(out);

    int w = warp_id;
    if (w >= n_windows) return;

    // Prefetch first window (window stride = 192 float4 = 3 rows x 64).
    {
        const float4* xin = xbase + (long long)w * 192;
        // fallthrough into loop prefetch registers below
    }
    const float4* xin0 = xbase + (long long)w * 192 + fv;
    float4 n0a = __ldcs(xin0 + 0 * 64), n0b = __ldcs(xin0 + 0 * 64 + 1);
    float4 n1a = __ldcs(xin0 + 1 * 64), n1b = __ldcs(xin0 + 1 * 64 + 1);
    float4 n2a = __ldcs(xin0 + 2 * 64), n2b = __ldcs(xin0 + 2 * 64 + 1);

    for (; w < n_windows; w += n_warps) {
        // Current window = last prefetch.
        float4 r0a = n0a, r0b = n0b;
        float4 r1a = n1a, r1b = n1b;
        float4 r2a = n2a, r2b = n2b;

        // Prefetch next window BEFORE the dependent compute chain.
        // Clamp index so loads are always issued (warp-uniform, no divergence).
        {
            int wn = w + n_warps;
            wn = (wn < n_windows) ? wn : w;  // last iter: reload self (harmless, L2 hit)
            const float4* nx = xbase + (long long)wn * 192 + fv;
            n0a = __ldcs(nx + 0 * 64); n0b = __ldcs(nx + 0 * 64 + 1);
            n1a = __ldcs(nx + 1 * 64); n1b = __ldcs(nx + 1 * 64 + 1);
            n2a = __ldcs(nx + 2 * 64); n2b = __ldcs(nx + 2 * 64 + 1);
        }

        // Scores: per-lane partials + butterfly reduce (all lanes get the sum).
        float s0 = warp_reduce_sum(dot8(r0a, r0b, wa, wb)) + bias;
        float s1 = warp_reduce_sum(dot8(r1a, r1b, wa, wb)) + bias;
        float s2 = warp_reduce_sum(dot8(r2a, r2b, wa, wb)) + bias;

        // Softmax over 3 scores.
        float m = fmaxf(s0, fmaxf(s1, s2));
        float e0 = __expf(s0 - m);
        float e1 = __expf(s1 - m);
        float e2 = __expf(s2 - m);
        float inv = 1.0f / (e0 + e1 + e2);
        float a0 = e0 * inv, a1 = e1 * inv, a2 = e2 * inv;

        // Weighted combine.
        float4 oa, ob;
        oa.x = fmaf(r2a.x, a2, fmaf(r1a.x, a1, r0a.x * a0));
        oa.y = fmaf(r2a.y, a2, fmaf(r1a.y, a1, r0a.y * a0));
        oa.z = fmaf(r2a.z, a2, fmaf(r1a.z, a1, r0a.z * a0));
        oa.w = fmaf(r2a.w, a2, fmaf(r1a.w, a1, r0a.w * a0));
        ob.x = fmaf(r2b.x, a2, fmaf(r1b.x, a1, r0b.x * a0));
        ob.y = fmaf(r2b.y, a2, fmaf(r1b.y, a1, r0b.y * a0));
        ob.z = fmaf(r2b.z, a2, fmaf(r1b.z, a1, r0b.z * a0));
        ob.w = fmaf(r2b.w, a2, fmaf(r1b.w, a1, r0b.w * a0));

        float4* o = obase + (long long)w * 64 + fv;
        __stcs(o,     oa);
        __stcs(o + 1, ob);
    }
}

extern "C" void kernel_launch(void* const* d_in, const int* in_sizes, int n_in,
                              void* d_out, int out_size) {
    const float* x  = (const float*)d_in[0];  // [32, 3072, 256]
    const float* Ww = (const float*)d_in[1];  // [256]
    const float* Wb = (const float*)d_in[2];  // [1]
    float* out = (float*)d_out;               // [32, 1024, 256, 1]

    const int n_windows = in_sizes[0] / (P_DIM * F_DIM);  // 32768
    const int blocks = NUM_SMS * BLOCKS_PER_SM;           // 444, exact-fit one wave

    gap_kernel<<<blocks, THREADS_PER_BLOCK>>>(x, Ww, Wb, out, n_windows);
}